// round 3
// baseline (speedup 1.0000x reference)
#include <cuda_runtime.h>
#include <cuda_bf16.h>
#include <cstdint>

// Static scratch (no allocations allowed). Sized for V <= 4M, n_he <= 8M.
__device__ int g_offsets[(4u << 20) + 1];   // exclusive prefix sums (+ total)
__device__ int g_cursor[4u << 20];          // histogram, then running cursors
__device__ int g_blocksums[4096];
__device__ int g_perm[8u << 20];            // edge indices sorted by vertex

// ---------------------------------------------------------------------------
// Pass A: histogram of vertex ids into g_cursor (int counts).
// ---------------------------------------------------------------------------
__global__ void hist_kernel(const int* __restrict__ ids, int n)
{
    int i = blockIdx.x * blockDim.x + threadIdx.x;
    if (i < n) atomicAdd(&g_cursor[__ldg(ids + i)], 1);
}

// ---------------------------------------------------------------------------
// Scan step 1: per-block (1024 elems) exclusive scan of counts -> g_offsets,
// block totals -> g_blocksums.
// ---------------------------------------------------------------------------
__global__ void scan1_kernel(int V)
{
    __shared__ int sh[1024];
    int i = blockIdx.x * 1024 + threadIdx.x;
    int v = (i < V) ? g_cursor[i] : 0;
    sh[threadIdx.x] = v;
    __syncthreads();
    for (int d = 1; d < 1024; d <<= 1) {
        int t = (threadIdx.x >= d) ? sh[threadIdx.x - d] : 0;
        __syncthreads();
        sh[threadIdx.x] += t;
        __syncthreads();
    }
    if (i < V) g_offsets[i] = sh[threadIdx.x] - v;   // exclusive
    if (threadIdx.x == 1023) g_blocksums[blockIdx.x] = sh[1023];
}

// ---------------------------------------------------------------------------
// Scan step 2: single-block exclusive scan of block sums (with carry loop).
// ---------------------------------------------------------------------------
__global__ void scan2_kernel(int nb)
{
    __shared__ int sh[1024];
    __shared__ int carry;
    if (threadIdx.x == 0) carry = 0;
    __syncthreads();
    for (int base = 0; base < nb; base += 1024) {
        int i = base + threadIdx.x;
        int v = (i < nb) ? g_blocksums[i] : 0;
        sh[threadIdx.x] = v;
        __syncthreads();
        for (int d = 1; d < 1024; d <<= 1) {
            int t = (threadIdx.x >= d) ? sh[threadIdx.x - d] : 0;
            __syncthreads();
            sh[threadIdx.x] += t;
            __syncthreads();
        }
        if (i < nb) g_blocksums[i] = sh[threadIdx.x] - v + carry;
        __syncthreads();
        if (threadIdx.x == 0) carry += sh[1023];
        __syncthreads();
    }
}

// ---------------------------------------------------------------------------
// Scan step 3: add block offsets; publish final offsets and a cursor copy.
// ---------------------------------------------------------------------------
__global__ void scan3_kernel(int V, int n_he)
{
    int i = blockIdx.x * 1024 + threadIdx.x;
    if (i < V) {
        int o = g_offsets[i] + g_blocksums[i >> 10];
        g_offsets[i] = o;
        g_cursor[i]  = o;   // overwrite counts with running cursor
    }
    if (i == 0) g_offsets[V] = n_he;
}

// ---------------------------------------------------------------------------
// Pass B: counting-sort of edge INDICES by vertex id.
// ---------------------------------------------------------------------------
__global__ void perm_kernel(const int* __restrict__ ids, int n)
{
    int i = blockIdx.x * blockDim.x + threadIdx.x;
    if (i < n) {
        int v = __ldg(ids + i);
        int pos = atomicAdd(&g_cursor[v], 1);
        g_perm[pos] = i;
    }
}

// ---------------------------------------------------------------------------
// Pass C: gather + mean. One warp per vertex, lane = feature (D = 32).
// Each edge row is one fully-coalesced 128B warp load. Output written once,
// scaled by 1/valence. Zero atomics on feature data.
// ---------------------------------------------------------------------------
__global__ void gather_kernel(const float* __restrict__ x,
                              float* __restrict__ out, int V)
{
    int w = (blockIdx.x * blockDim.x + threadIdx.x) >> 5;
    int lane = threadIdx.x & 31;
    if (w >= V) return;

    int beg = __ldg(&g_offsets[w]);
    int end = __ldg(&g_offsets[w + 1]);

    float acc = 0.0f;
    for (int base = beg; base < end; base += 32) {
        int j = base + lane;
        int e = (j < end) ? __ldg(&g_perm[j]) : 0;
        int cnt = end - base; if (cnt > 32) cnt = 32;
        #pragma unroll 8
        for (int k = 0; k < cnt; k++) {
            int ee = __shfl_sync(0xffffffffu, e, k);
            acc += __ldg(x + (long long)ee * 32 + lane);
        }
    }
    float inv = 1.0f / fmaxf((float)(end - beg), 1.0f);
    out[(long long)w * 32 + lane] = acc * inv;
}

extern "C" void kernel_launch(void* const* d_in, const int* in_sizes, int n_in,
                              void* d_out, int out_size)
{
    const float* x   = (const float*)d_in[0];
    const int*   ids = (const int*)d_in[1];

    int n_he = in_sizes[1];                     // element count of vertex_ids
    int V    = (int)((long long)out_size / 32); // output is [V, 32]

    float* out = (float*)d_out;

    // Zero the histogram (g_cursor doubles as counts).
    void* cursor_ptr = nullptr;
    cudaGetSymbolAddress(&cursor_ptr, g_cursor);
    cudaMemsetAsync(cursor_ptr, 0, (size_t)V * sizeof(int));

    // Pass A: histogram.
    hist_kernel<<<(n_he + 255) / 256, 256>>>(ids, n_he);

    // Exclusive scan (3 small kernels).
    int nb = (V + 1023) / 1024;
    scan1_kernel<<<nb, 1024>>>(V);
    scan2_kernel<<<1, 1024>>>(nb);
    scan3_kernel<<<nb, 1024>>>(V, n_he);

    // Pass B: permutation (edge indices grouped by vertex).
    perm_kernel<<<(n_he + 255) / 256, 256>>>(ids, n_he);

    // Pass C: gather + mean, one warp per vertex.
    {
        int threads = 256;                       // 8 warps/block
        int blocks = (V + 7) / 8;
        gather_kernel<<<blocks, threads>>>(x, out, V);
    }
}

// round 4
// speedup vs baseline: 1.9056x; 1.9056x over previous
#include <cuda_runtime.h>
#include <cuda_bf16.h>
#include <cstdint>

// Static scratch (no allocations allowed). Sized for V <= 4M, n_he <= 8M.
__device__ int g_offsets[(4u << 20) + 1];   // exclusive prefix sums (+ total)
__device__ int g_cursor[4u << 20];          // histogram, then running cursors
__device__ int g_blocksums[4096];
__device__ int g_perm[8u << 20];            // edge indices grouped by vertex

// ---------------------------------------------------------------------------
// Pass A: histogram of vertex ids.
// ---------------------------------------------------------------------------
__global__ void hist_kernel(const int* __restrict__ ids, int n)
{
    int i = blockIdx.x * blockDim.x + threadIdx.x;
    if (i < n) atomicAdd(&g_cursor[__ldg(ids + i)], 1);
}

// ---------------------------------------------------------------------------
// Exclusive scan, step 1: per-block scan of counts; block totals out.
// ---------------------------------------------------------------------------
__global__ void scan1_kernel(int V)
{
    __shared__ int sh[1024];
    int i = blockIdx.x * 1024 + threadIdx.x;
    int v = (i < V) ? g_cursor[i] : 0;
    sh[threadIdx.x] = v;
    __syncthreads();
    for (int d = 1; d < 1024; d <<= 1) {
        int t = (threadIdx.x >= d) ? sh[threadIdx.x - d] : 0;
        __syncthreads();
        sh[threadIdx.x] += t;
        __syncthreads();
    }
    if (i < V) g_offsets[i] = sh[threadIdx.x] - v;   // exclusive
    if (threadIdx.x == 1023) g_blocksums[blockIdx.x] = sh[1023];
}

// ---------------------------------------------------------------------------
// Exclusive scan, step 2: single-block scan of block sums (carry loop).
// ---------------------------------------------------------------------------
__global__ void scan2_kernel(int nb)
{
    __shared__ int sh[1024];
    __shared__ int carry;
    if (threadIdx.x == 0) carry = 0;
    __syncthreads();
    for (int base = 0; base < nb; base += 1024) {
        int i = base + threadIdx.x;
        int v = (i < nb) ? g_blocksums[i] : 0;
        sh[threadIdx.x] = v;
        __syncthreads();
        for (int d = 1; d < 1024; d <<= 1) {
            int t = (threadIdx.x >= d) ? sh[threadIdx.x - d] : 0;
            __syncthreads();
            sh[threadIdx.x] += t;
            __syncthreads();
        }
        if (i < nb) g_blocksums[i] = sh[threadIdx.x] - v + carry;
        __syncthreads();
        if (threadIdx.x == 0) carry += sh[1023];
        __syncthreads();
    }
}

// ---------------------------------------------------------------------------
// Exclusive scan, step 3: add block offsets; publish offsets + cursor copy.
// ---------------------------------------------------------------------------
__global__ void scan3_kernel(int V, int n_he)
{
    int i = blockIdx.x * 1024 + threadIdx.x;
    if (i < V) {
        int o = g_offsets[i] + g_blocksums[i >> 10];
        g_offsets[i] = o;
        g_cursor[i]  = o;
    }
    if (i == 0) g_offsets[V] = n_he;
}

// ---------------------------------------------------------------------------
// Pass B: counting-sort of edge INDICES by vertex id.
// ---------------------------------------------------------------------------
__global__ void perm_kernel(const int* __restrict__ ids, int n)
{
    int i = blockIdx.x * blockDim.x + threadIdx.x;
    if (i < n) {
        int v = __ldg(ids + i);
        int pos = atomicAdd(&g_cursor[v], 1);
        g_perm[pos] = i;
    }
}

// ---------------------------------------------------------------------------
// Pass C: gather + mean, restructured for memory-level parallelism.
// 8 threads per vertex; thread s covers features [4s, 4s+4) as one float4.
// The 8-thread group reads each edge row as one full 128B line.
// Inner loop unrolled x4 with indices prefetched -> 4 independent float4
// loads in flight per thread (16 x 128B lines per warp).
// ---------------------------------------------------------------------------
__global__ void gather_kernel(const float4* __restrict__ x4,
                              float* __restrict__ out, int V)
{
    long long t = (long long)blockIdx.x * blockDim.x + threadIdx.x;
    int v = (int)(t >> 3);          // vertex (8 threads per vertex)
    int s = (int)(t & 7);           // quad index within the 32-dim row
    if (v >= V) return;

    int beg = __ldg(&g_offsets[v]);
    int end = __ldg(&g_offsets[v + 1]);
    int deg = end - beg;

    float4 acc = make_float4(0.f, 0.f, 0.f, 0.f);

    int k = beg;
    for (; k + 4 <= end; k += 4) {
        // Prefetch indices first (L1-broadcast across the 8-thread group).
        int e0 = __ldg(&g_perm[k]);
        int e1 = __ldg(&g_perm[k + 1]);
        int e2 = __ldg(&g_perm[k + 2]);
        int e3 = __ldg(&g_perm[k + 3]);
        // 4 independent 16B loads in flight.
        float4 a0 = __ldg(x4 + (long long)e0 * 8 + s);
        float4 a1 = __ldg(x4 + (long long)e1 * 8 + s);
        float4 a2 = __ldg(x4 + (long long)e2 * 8 + s);
        float4 a3 = __ldg(x4 + (long long)e3 * 8 + s);
        acc.x += a0.x + a1.x + a2.x + a3.x;
        acc.y += a0.y + a1.y + a2.y + a3.y;
        acc.z += a0.z + a1.z + a2.z + a3.z;
        acc.w += a0.w + a1.w + a2.w + a3.w;
    }
    for (; k < end; k++) {
        int e = __ldg(&g_perm[k]);
        float4 a = __ldg(x4 + (long long)e * 8 + s);
        acc.x += a.x; acc.y += a.y; acc.z += a.z; acc.w += a.w;
    }

    float inv = 1.0f / fmaxf((float)deg, 1.0f);
    float4 o = make_float4(acc.x * inv, acc.y * inv, acc.z * inv, acc.w * inv);
    ((float4*)out)[(long long)v * 8 + s] = o;
}

extern "C" void kernel_launch(void* const* d_in, const int* in_sizes, int n_in,
                              void* d_out, int out_size)
{
    const float4* x4  = (const float4*)d_in[0];
    const int*    ids = (const int*)d_in[1];

    int n_he = in_sizes[1];                     // element count of vertex_ids
    int V    = (int)((long long)out_size / 32); // output is [V, 32]

    float* out = (float*)d_out;

    // Zero the histogram (g_cursor doubles as counts).
    void* cursor_ptr = nullptr;
    cudaGetSymbolAddress(&cursor_ptr, g_cursor);
    cudaMemsetAsync(cursor_ptr, 0, (size_t)V * sizeof(int));

    // Pass A: histogram.
    hist_kernel<<<(n_he + 255) / 256, 256>>>(ids, n_he);

    // Exclusive scan.
    int nb = (V + 1023) / 1024;
    scan1_kernel<<<nb, 1024>>>(V);
    scan2_kernel<<<1, 1024>>>(nb);
    scan3_kernel<<<nb, 1024>>>(V, n_he);

    // Pass B: permutation (edge indices grouped by vertex).
    perm_kernel<<<(n_he + 255) / 256, 256>>>(ids, n_he);

    // Pass C: gather + mean, 8 threads per vertex.
    {
        long long total = (long long)V * 8;
        int threads = 256;
        int blocks = (int)((total + threads - 1) / threads);
        gather_kernel<<<blocks, threads>>>(x4, out, V);
    }
}

// round 5
// speedup vs baseline: 2.0320x; 1.0663x over previous
#include <cuda_runtime.h>
#include <cuda_bf16.h>
#include <cstdint>

// Static scratch (no allocations allowed). Sized for V <= 4M, n_he <= 8M.
__device__ int g_counts[4u << 20];          // histogram
__device__ int g_offsets[4u << 20];         // excl offsets -> (post-perm) incl ends
__device__ int g_blocksums[4096];
__device__ int g_perm[8u << 20];            // edge indices grouped by vertex

// ---------------------------------------------------------------------------
// Warp-shuffle inclusive scan helper.
// ---------------------------------------------------------------------------
__device__ __forceinline__ int warp_incl_scan(int v)
{
    #pragma unroll
    for (int d = 1; d < 32; d <<= 1) {
        int t = __shfl_up_sync(0xffffffffu, v, d);
        if ((threadIdx.x & 31) >= d) v += t;
    }
    return v;
}

// ---------------------------------------------------------------------------
// Pass A: histogram of vertex ids.
// ---------------------------------------------------------------------------
__global__ void hist_kernel(const int* __restrict__ ids, int n)
{
    int i = blockIdx.x * blockDim.x + threadIdx.x;
    if (i < n) atomicAdd(&g_counts[__ldg(ids + i)], 1);
}

// ---------------------------------------------------------------------------
// Scan step 1: per-block (1024) exclusive scan of counts; block totals out.
// ---------------------------------------------------------------------------
__global__ void scan1_kernel(int V)
{
    __shared__ int wsum[32];
    int i = blockIdx.x * 1024 + threadIdx.x;
    int v = (i < V) ? g_counts[i] : 0;
    int incl = warp_incl_scan(v);
    int lane = threadIdx.x & 31, wid = threadIdx.x >> 5;
    if (lane == 31) wsum[wid] = incl;
    __syncthreads();
    if (wid == 0) {
        int w = wsum[lane];
        int ws = warp_incl_scan(w);
        wsum[lane] = ws - w;                  // exclusive warp offsets
    }
    __syncthreads();
    int excl = incl - v + wsum[wid];
    if (i < V) g_offsets[i] = excl;
    if (threadIdx.x == 1023) g_blocksums[blockIdx.x] = excl + v;   // block total
}

// ---------------------------------------------------------------------------
// Scan step 2: single-block exclusive scan of block sums (carry loop).
// ---------------------------------------------------------------------------
__global__ void scan2_kernel(int nb)
{
    __shared__ int wsum[32];
    __shared__ int carry_s;
    if (threadIdx.x == 0) carry_s = 0;
    __syncthreads();
    for (int base = 0; base < nb; base += 1024) {
        int i = base + threadIdx.x;
        int v = (i < nb) ? g_blocksums[i] : 0;
        int incl = warp_incl_scan(v);
        int lane = threadIdx.x & 31, wid = threadIdx.x >> 5;
        if (lane == 31) wsum[wid] = incl;
        __syncthreads();
        if (wid == 0) {
            int w = wsum[lane];
            int ws = warp_incl_scan(w);
            wsum[lane] = ws - w;
        }
        __syncthreads();
        int excl = incl - v + wsum[wid] + carry_s;
        if (i < nb) g_blocksums[i] = excl;
        __syncthreads();                       // everyone has consumed carry_s
        if (threadIdx.x == 1023) carry_s = excl + v;
        __syncthreads();
    }
}

// ---------------------------------------------------------------------------
// Scan step 3: add block offsets in place (final exclusive offsets).
// ---------------------------------------------------------------------------
__global__ void scan3_kernel(int V)
{
    int i = blockIdx.x * 1024 + threadIdx.x;
    if (i < V) g_offsets[i] += g_blocksums[i >> 10];
}

// ---------------------------------------------------------------------------
// Pass B: counting-sort of edge INDICES by vertex id, bumping g_offsets
// directly. Post-condition: g_offsets[v] == inclusive end of segment v,
// i.e. segment v == [g_offsets[v-1], g_offsets[v]).
// ---------------------------------------------------------------------------
__global__ void perm_kernel(const int* __restrict__ ids, int n)
{
    int i = blockIdx.x * blockDim.x + threadIdx.x;
    if (i < n) {
        int v = __ldg(ids + i);
        int pos = atomicAdd(&g_offsets[v], 1);
        g_perm[pos] = i;
    }
}

// ---------------------------------------------------------------------------
// Pass C: gather + mean. 8 threads per vertex; thread s covers features
// [4s, 4s+4) as one float4 (8-thread group = one 128B edge row).
// Edges processed in predicated 8-wide chunks: all 8 row loads are
// independent and issue back-to-back (no serial tail for deg <= 8,
// which covers ~85% of Poisson(6) vertices).
// ---------------------------------------------------------------------------
__global__ void gather_kernel(const float4* __restrict__ x4,
                              float4* __restrict__ out4, int V)
{
    long long t = (long long)blockIdx.x * blockDim.x + threadIdx.x;
    int v = (int)(t >> 3);          // vertex
    int s = (int)(t & 7);           // quad index within the 32-dim row
    if (v >= V) return;

    int beg = (v == 0) ? 0 : __ldg(&g_offsets[v - 1]);
    int end = __ldg(&g_offsets[v]);
    int deg = end - beg;

    float4 acc = make_float4(0.f, 0.f, 0.f, 0.f);

    for (int base = beg; base < end; base += 8) {
        int e[8];
        #pragma unroll
        for (int u = 0; u < 8; u++) {
            int j = base + u;
            e[u] = (j < end) ? __ldg(&g_perm[j]) : -1;
        }
        #pragma unroll
        for (int u = 0; u < 8; u++) {
            if (e[u] >= 0) {
                float4 a = __ldg(x4 + (long long)e[u] * 8 + s);
                acc.x += a.x; acc.y += a.y; acc.z += a.z; acc.w += a.w;
            }
        }
    }

    float inv = 1.0f / fmaxf((float)deg, 1.0f);
    out4[(long long)v * 8 + s] =
        make_float4(acc.x * inv, acc.y * inv, acc.z * inv, acc.w * inv);
}

extern "C" void kernel_launch(void* const* d_in, const int* in_sizes, int n_in,
                              void* d_out, int out_size)
{
    const float4* x4  = (const float4*)d_in[0];
    const int*    ids = (const int*)d_in[1];

    int n_he = in_sizes[1];                     // element count of vertex_ids
    int V    = (int)((long long)out_size / 32); // output is [V, 32]

    // Zero the histogram.
    void* counts_ptr = nullptr;
    cudaGetSymbolAddress(&counts_ptr, g_counts);
    cudaMemsetAsync(counts_ptr, 0, (size_t)V * sizeof(int));

    // Pass A: histogram.
    hist_kernel<<<(n_he + 255) / 256, 256>>>(ids, n_he);

    // Exclusive scan (shuffle-based).
    int nb = (V + 1023) / 1024;
    scan1_kernel<<<nb, 1024>>>(V);
    scan2_kernel<<<1, 1024>>>(nb);
    scan3_kernel<<<nb, 1024>>>(V);

    // Pass B: permutation; g_offsets becomes inclusive segment ends.
    perm_kernel<<<(n_he + 255) / 256, 256>>>(ids, n_he);

    // Pass C: gather + mean, 8 threads per vertex.
    {
        long long total = (long long)V * 8;
        int threads = 256;
        int blocks = (int)((total + threads - 1) / threads);
        gather_kernel<<<blocks, threads>>>(x4, (float4*)d_out, V);
    }
}